// round 5
// baseline (speedup 1.0000x reference)
#include <cuda_runtime.h>

#define SS 17
#define AA 5
#define CC 20
#define BIMG 256
#define GG 32
#define HW (SS*SS)          // 289
#define NPA (HW*AA)         // 1445
#define NTHREADS 128
#define SPLIT 12            // CTAs per image
#define CHUNK ((NPA + SPLIT - 1) / SPLIT)   // 121  (<= NTHREADS, one slot per thread)

__global__ void zero_out_kernel(float* out) { *out = 0.0f; }

__global__ __launch_bounds__(NTHREADS, 10)
void yolo_loss_kernel(const float* __restrict__ bbox_pred,
                      const float* __restrict__ iou_pred,
                      const float* __restrict__ score_pred,
                      const float* __restrict__ targets,
                      const float* __restrict__ anchors,
                      float* __restrict__ out)
{
    const int blk  = blockIdx.x;
    const int b    = blk / SPLIT;
    const int part = blk - b * SPLIT;
    const int tid  = threadIdx.x;

    __shared__ float4       gbox[GG];        // x1,y1,x2,y2
    __shared__ float        garea[GG];
    __shared__ float        thr06[GG];       // 0.6 * garea
    __shared__ float4       tarv[GG];        // off_x, off_y, w, h
    __shared__ int          gcls[GG];
    __shared__ unsigned int gwin[GG];        // packed ilo|ihi<<8|jlo<<16|jhi<<24
    __shared__ unsigned int cellmask[HW];    // GT bitmask per cell (only own range built)
    __shared__ short        selmap[NPA];
    __shared__ float        anc[AA][2];
    __shared__ float        red[NTHREADS/32];

    const int start = part * CHUNK;
    const int end   = (start + CHUNK < NPA) ? start + CHUNK : NPA;
    const int cell_lo = start / AA;
    const int cell_hi = (end - 1) / AA;

    for (int i = start + tid; i < end; i += NTHREADS) selmap[i] = -1;
    if (tid < AA) {
        anc[tid][0] = anchors[tid*2+0] / 17.0f;
        anc[tid][1] = anchors[tid*2+1] / 17.0f;
    }
    __syncthreads();

    if (tid < GG) {
        const float* t = targets + ((size_t)b*GG + tid)*6;
        int   cls = (int)t[1];
        float x1 = t[2], y1 = t[3], x2 = t[4], y2 = t[5];
        gbox[tid] = make_float4(x1, y1, x2, y2);
        float w = x2 - x1, h = y2 - y1;
        float ar = w * h;
        garea[tid] = ar;
        thr06[tid] = 0.6f * ar;
        float cxs = (x1 + x2) * 0.5f * (float)SS;
        float cys = (y1 + y2) * 0.5f * (float)SS;
        int ci = (int)floorf(cxs), cj = (int)floorf(cys);
        tarv[tid] = make_float4(cxs - (float)ci, cys - (float)cj, w, h);
        gcls[tid] = cls;

        // window of cells where IoU > 0.6 is geometrically possible:
        // |cx - gcx| < 2.347*gw  (derived from IoU>0.6); margin 2.36 for fp slack
        const float MS = 2.36f * 17.0f;
        int ilo = (int)floorf(cxs - MS*w); if (ilo < 0) ilo = 0;
        int ihi = (int)floorf(cxs + MS*w); if (ihi > SS-1) ihi = SS-1;
        int jlo = (int)floorf(cys - MS*h); if (jlo < 0) jlo = 0;
        int jhi = (int)floorf(cys + MS*h); if (jhi > SS-1) jhi = SS-1;
        gwin[tid] = (unsigned)ilo | ((unsigned)ihi << 8)
                  | ((unsigned)jlo << 16) | ((unsigned)jhi << 24);

        // anchor argmax (first-max tiebreak)
        int best_a = 0; float best = -1.0f;
        #pragma unroll
        for (int a = 0; a < AA; a++) {
            float aw = anc[a][0], ah = anc[a][1];
            float inter = fminf(aw, w) * fminf(ah, h);
            float aiou  = inter / (aw*ah + ar - inter);
            if (aiou > best) { best = aiou; best_a = a; }
        }
        int cell = ci * SS + cj;
        selmap[cell*AA + best_a] = (short)tid;  // out-of-range writes never read
    }
    __syncthreads();

    // build per-cell GT masks for this CTA's cell range
    for (int c = cell_lo + tid; c <= cell_hi; c += NTHREADS) {
        int ci = c / SS;
        int cj = c - ci * SS;
        unsigned msk = 0;
        #pragma unroll
        for (int g = 0; g < GG; g++) {
            unsigned w = gwin[g];
            unsigned ilo = w & 0xffu, ihi = (w >> 8) & 0xffu;
            unsigned jlo = (w >> 16) & 0xffu, jhi = (w >> 24) & 0xffu;
            bool in = ((unsigned)(ci - ilo) <= (ihi - ilo)) &
                      ((unsigned)(cj - jlo) <= (jhi - jlo));
            msk |= (in ? 1u : 0u) << g;
        }
        cellmask[c] = msk;
    }
    __syncthreads();

    const float* bb = bbox_pred  + (size_t)b * NPA * 4;
    const float* ip = iou_pred   + (size_t)b * NPA;
    const float* sp = score_pred + (size_t)b * NPA * CC;

    const float invS = 1.0f / 17.0f;
    float acc = 0.0f;

    // exactly one slot per thread (CHUNK <= NTHREADS); straight-line, warp-uniform
    {
        int  idx   = start + tid;
        bool valid = idx < end;
        int  sidx  = valid ? idx : start;

        float4 p = reinterpret_cast<const float4*>(bb)[sidx];
        int hw = sidx / AA;
        int a  = sidx - hw*AA;
        int i  = hw / SS;
        int j  = hw - i*SS;

        float aw = p.z * anc[a][0];
        float ah = p.w * anc[a][1];
        float px1 = (p.x + (float)i - 0.5f*aw) * invS;
        float px2 = (p.x + (float)i + 0.5f*aw) * invS;
        float py1 = (p.y + (float)j - 0.5f*ah) * invS;
        float py2 = (p.y + (float)j + 0.5f*ah) * invS;
        float parea = (aw * invS) * (ah * invS);

        unsigned mymask = valid ? cellmask[hw] : 0u;
        unsigned umask  = __reduce_or_sync(0xffffffffu, mymask);

        // m = max_k (1.6*inter_k - 0.6*garea_k); best_iou > 0.6 <=> m > 0.6*parea
        float m = -3.402823e38f;
        while (umask) {
            int k = __ffs(umask) - 1;
            umask &= umask - 1;
            float4 gb = gbox[k];                  // uniform k -> broadcast
            float lx = fmaxf(px1, gb.x);
            float ly = fmaxf(py1, gb.y);
            float rx = fminf(px2, gb.z);
            float ry = fminf(py2, gb.w);
            float iw = fmaxf(rx - lx, 0.0f);
            float ih = fmaxf(ry - ly, 0.0f);
            float inter = iw * ih;
            m = fmaxf(m, fmaf(inter, 1.6f, -thr06[k]));
        }

        if (valid) {
            float ipv = ip[sidx];
            int   g   = (int)selmap[sidx];

            if (g < 0) {
                float d0 = 0.01f*(p.x - 0.5f);
                float d1 = 0.01f*(p.y - 0.5f);
                float d2 = 0.01f*(p.z - 1.0f);
                float d3 = 0.01f*(p.w - 1.0f);
                acc += d0*d0 + d1*d1 + d2*d2 + d3*d3;
                if (m <= 0.6f * parea) {
                    float q = ipv * ipv;
                    acc += q * q;
                }
            } else {
                float4 gb = gbox[g];
                float lx = fmaxf(px1, gb.x);
                float ly = fmaxf(py1, gb.y);
                float rx = fminf(px2, gb.z);
                float ry = fminf(py2, gb.w);
                float iw = fmaxf(rx - lx, 0.0f);
                float ih = fmaxf(ry - ly, 0.0f);
                float inter = iw * ih;
                float iou_t = inter / (parea + garea[g] - inter);

                float4 tv = tarv[g];
                float d0 = p.x - tv.x;
                float d1 = p.y - tv.y;
                float d2 = p.z - tv.z;
                float d3 = p.w - tv.w;
                acc += d0*d0 + d1*d1 + d2*d2 + d3*d3;

                float mm = 5.0f * (1.0f - ipv);
                float d  = ipv - iou_t;
                acc += (mm*mm) * (d*d);

                int cls = gcls[g];
                const float* srow = sp + (size_t)sidx * CC;
                #pragma unroll
                for (int c = 0; c < CC; c++) {
                    float t  = (c == cls) ? 1.0f : 0.0f;
                    float dd = srow[c] - t;
                    acc += dd * dd;
                }
            }
        }
    }

    #pragma unroll
    for (int off = 16; off; off >>= 1)
        acc += __shfl_down_sync(0xffffffffu, acc, off);
    if ((tid & 31) == 0) red[tid >> 5] = acc;
    __syncthreads();
    if (tid < NTHREADS/32) {
        float v = red[tid];
        #pragma unroll
        for (int off = (NTHREADS/64); off; off >>= 1)
            v += __shfl_down_sync(0xffffffffu, v, off);
        if (tid == 0) atomicAdd(out, v * (1.0f / (float)GG));
    }
}

extern "C" void kernel_launch(void* const* d_in, const int* in_sizes, int n_in,
                              void* d_out, int out_size)
{
    const float* bbox    = (const float*)d_in[0];
    const float* iou     = (const float*)d_in[1];
    const float* score   = (const float*)d_in[2];
    const float* targets = (const float*)d_in[3];
    const float* anchors = (const float*)d_in[4];
    float* out = (float*)d_out;

    zero_out_kernel<<<1, 1>>>(out);
    yolo_loss_kernel<<<BIMG * SPLIT, NTHREADS>>>(bbox, iou, score, targets, anchors, out);
}

// round 6
// speedup vs baseline: 1.0376x; 1.0376x over previous
#include <cuda_runtime.h>

#define SS 17
#define AA 5
#define CC 20
#define BIMG 256
#define GG 32
#define HW (SS*SS)          // 289
#define NPA (HW*AA)         // 1445
#define NTHREADS 128
#define NWARPS (NTHREADS/32)
#define SPLIT 12            // CTAs per image
#define CHUNK ((NPA + SPLIT - 1) / SPLIT)   // 121 (<= NTHREADS: one slot per thread)

__global__ void zero_out_kernel(float* out) { *out = 0.0f; }

__global__ __launch_bounds__(NTHREADS, 10)
void yolo_loss_kernel(const float* __restrict__ bbox_pred,
                      const float* __restrict__ iou_pred,
                      const float* __restrict__ score_pred,
                      const float* __restrict__ targets,
                      const float* __restrict__ anchors,
                      float* __restrict__ out)
{
    const int blk  = blockIdx.x;
    const int b    = blk / SPLIT;
    const int part = blk - b * SPLIT;
    const int tid  = threadIdx.x;
    const int wid  = tid >> 5;
    const int lane = tid & 31;

    __shared__ float4       gbox[GG];        // x1,y1,x2,y2
    __shared__ float        garea[GG];
    __shared__ float        thr06[GG];       // 0.6 * garea
    __shared__ float4       tarv[GG];        // off_x, off_y, w, h
    __shared__ int          gcls[GG];
    __shared__ unsigned int gwin[GG];        // packed ilo|ihi<<8|jlo<<16|jhi<<24
    __shared__ unsigned int cellmask[HW];
    __shared__ short        selmap[NPA];
    __shared__ float        anc[AA][2];
    __shared__ float4       wlist[NWARPS][GG+4];  // dense candidate boxes per warp
    __shared__ float        wthr[NWARPS][GG+4];   // matching 0.6*garea
    __shared__ float        red[NWARPS];

    const int start = part * CHUNK;
    const int end   = (start + CHUNK < NPA) ? start + CHUNK : NPA;
    const int cell_lo = start / AA;
    const int cell_hi = (end - 1) / AA;

    for (int i = start + tid; i < end; i += NTHREADS) selmap[i] = -1;
    if (tid < AA) {
        anc[tid][0] = anchors[tid*2+0] / 17.0f;
        anc[tid][1] = anchors[tid*2+1] / 17.0f;
    }
    __syncthreads();

    if (tid < GG) {
        const float* t = targets + ((size_t)b*GG + tid)*6;
        int   cls = (int)t[1];
        float x1 = t[2], y1 = t[3], x2 = t[4], y2 = t[5];
        gbox[tid] = make_float4(x1, y1, x2, y2);
        float w = x2 - x1, h = y2 - y1;
        float ar = w * h;
        garea[tid] = ar;
        thr06[tid] = 0.6f * ar;
        float cxs = (x1 + x2) * 0.5f * (float)SS;
        float cys = (y1 + y2) * 0.5f * (float)SS;
        int ci = (int)floorf(cxs), cj = (int)floorf(cys);
        tarv[tid] = make_float4(cxs - (float)ci, cys - (float)cj, w, h);
        gcls[tid] = cls;

        // cells where IoU>0.6 is geometrically possible: |cx-gcx| < 2.347*gw
        const float MS = 2.36f * 17.0f;
        int ilo = (int)floorf(cxs - MS*w); if (ilo < 0) ilo = 0;
        int ihi = (int)floorf(cxs + MS*w); if (ihi > SS-1) ihi = SS-1;
        int jlo = (int)floorf(cys - MS*h); if (jlo < 0) jlo = 0;
        int jhi = (int)floorf(cys + MS*h); if (jhi > SS-1) jhi = SS-1;
        gwin[tid] = (unsigned)ilo | ((unsigned)ihi << 8)
                  | ((unsigned)jlo << 16) | ((unsigned)jhi << 24);

        // anchor argmax (first-max tiebreak)
        int best_a = 0; float best = -1.0f;
        #pragma unroll
        for (int a = 0; a < AA; a++) {
            float aw = anc[a][0], ah = anc[a][1];
            float inter = fminf(aw, w) * fminf(ah, h);
            float aiou  = inter / (aw*ah + ar - inter);
            if (aiou > best) { best = aiou; best_a = a; }
        }
        int cell = ci * SS + cj;
        selmap[cell*AA + best_a] = (short)tid;  // out-of-range writes never read
    }
    __syncthreads();

    // per-cell GT candidate masks for this CTA's cells
    for (int c = cell_lo + tid; c <= cell_hi; c += NTHREADS) {
        int ci = c / SS;
        int cj = c - ci * SS;
        unsigned msk = 0;
        #pragma unroll
        for (int g = 0; g < GG; g++) {
            unsigned w = gwin[g];
            unsigned ilo = w & 0xffu, ihi = (w >> 8) & 0xffu;
            unsigned jlo = (w >> 16) & 0xffu, jhi = (w >> 24) & 0xffu;
            bool in = ((unsigned)(ci - ilo) <= (ihi - ilo)) &
                      ((unsigned)(cj - jlo) <= (jhi - jlo));
            msk |= (in ? 1u : 0u) << g;
        }
        cellmask[c] = msk;
    }
    __syncthreads();

    const float* bb = bbox_pred  + (size_t)b * NPA * 4;
    const float* ip = iou_pred   + (size_t)b * NPA;
    const float* sp = score_pred + (size_t)b * NPA * CC;

    const float invS = 1.0f / 17.0f;
    float acc = 0.0f;

    {
        int  idx   = start + tid;
        bool valid = idx < end;
        int  sidx  = valid ? idx : start;

        float4 p = reinterpret_cast<const float4*>(bb)[sidx];
        int hw = sidx / AA;
        int a  = sidx - hw*AA;
        int i  = hw / SS;
        int j  = hw - i*SS;

        float aw = p.z * anc[a][0];
        float ah = p.w * anc[a][1];
        float px1 = (p.x + (float)i - 0.5f*aw) * invS;
        float px2 = (p.x + (float)i + 0.5f*aw) * invS;
        float py1 = (p.y + (float)j - 0.5f*ah) * invS;
        float py2 = (p.y + (float)j + 0.5f*ah) * invS;
        float parea = (aw * invS) * (ah * invS);

        // warp-union candidate mask -> dense shared list (parallel compaction)
        unsigned mymask = valid ? cellmask[hw] : 0u;
        unsigned umask  = __reduce_or_sync(0xffffffffu, mymask);
        int n = __popc(umask);
        if (umask & (1u << lane)) {
            int pos = __popc(umask & ((1u << lane) - 1u));
            wlist[wid][pos] = gbox[lane];
            wthr[wid][pos]  = thr06[lane];
        }
        if (lane < 4) {   // sentinel padding: zero-intersection box, huge thr
            wlist[wid][n + lane] = make_float4(2.0f, 2.0f, 2.0f, 2.0f);
            wthr[wid][n + lane]  = 1e30f;
        }
        __syncwarp();

        // m = max_k (1.6*inter_k - 0.6*garea_k); best_iou > 0.6 <=> m > 0.6*parea
        float m = -3.402823e38f;
        int n4 = (n + 3) & ~3;
        for (int t = 0; t < n4; t += 4) {
            #pragma unroll
            for (int u = 0; u < 4; u++) {
                float4 gb = wlist[wid][t + u];
                float th  = wthr[wid][t + u];
                float lx = fmaxf(px1, gb.x);
                float ly = fmaxf(py1, gb.y);
                float rx = fminf(px2, gb.z);
                float ry = fminf(py2, gb.w);
                float iw = fmaxf(rx - lx, 0.0f);
                float ih = fmaxf(ry - ly, 0.0f);
                float inter = iw * ih;
                m = fmaxf(m, fmaf(inter, 1.6f, -th));
            }
        }

        if (valid) {
            float ipv = ip[sidx];
            int   g   = (int)selmap[sidx];

            if (g < 0) {
                float d0 = 0.01f*(p.x - 0.5f);
                float d1 = 0.01f*(p.y - 0.5f);
                float d2 = 0.01f*(p.z - 1.0f);
                float d3 = 0.01f*(p.w - 1.0f);
                acc += d0*d0 + d1*d1 + d2*d2 + d3*d3;
                if (m <= 0.6f * parea) {
                    float q = ipv * ipv;
                    acc += q * q;
                }
            } else {
                float4 gb = gbox[g];
                float lx = fmaxf(px1, gb.x);
                float ly = fmaxf(py1, gb.y);
                float rx = fminf(px2, gb.z);
                float ry = fminf(py2, gb.w);
                float iw = fmaxf(rx - lx, 0.0f);
                float ih = fmaxf(ry - ly, 0.0f);
                float inter = iw * ih;
                float iou_t = inter / (parea + garea[g] - inter);

                float4 tv = tarv[g];
                float d0 = p.x - tv.x;
                float d1 = p.y - tv.y;
                float d2 = p.z - tv.z;
                float d3 = p.w - tv.w;
                acc += d0*d0 + d1*d1 + d2*d2 + d3*d3;

                float mm = 5.0f * (1.0f - ipv);
                float d  = ipv - iou_t;
                acc += (mm*mm) * (d*d);

                int cls = gcls[g];
                const float* srow = sp + (size_t)sidx * CC;
                #pragma unroll
                for (int c = 0; c < CC; c++) {
                    float t2 = (c == cls) ? 1.0f : 0.0f;
                    float dd = srow[c] - t2;
                    acc += dd * dd;
                }
            }
        }
    }

    #pragma unroll
    for (int off = 16; off; off >>= 1)
        acc += __shfl_down_sync(0xffffffffu, acc, off);
    if ((tid & 31) == 0) red[tid >> 5] = acc;
    __syncthreads();
    if (tid < NWARPS) {
        float v = red[tid];
        #pragma unroll
        for (int off = (NWARPS/2); off; off >>= 1)
            v += __shfl_down_sync(0xffffffffu, v, off);
        if (tid == 0) atomicAdd(out, v * (1.0f / (float)GG));
    }
}

extern "C" void kernel_launch(void* const* d_in, const int* in_sizes, int n_in,
                              void* d_out, int out_size)
{
    const float* bbox    = (const float*)d_in[0];
    const float* iou     = (const float*)d_in[1];
    const float* score   = (const float*)d_in[2];
    const float* targets = (const float*)d_in[3];
    const float* anchors = (const float*)d_in[4];
    float* out = (float*)d_out;

    zero_out_kernel<<<1, 1>>>(out);
    yolo_loss_kernel<<<BIMG * SPLIT, NTHREADS>>>(bbox, iou, score, targets, anchors, out);
}

// round 8
// speedup vs baseline: 2.7689x; 2.6686x over previous
#include <cuda_runtime.h>

#define SS 17
#define AA 5
#define CC 20
#define BIMG 256
#define GG 32
#define HW (SS*SS)          // 289
#define NPA (HW*AA)         // 1445
#define NTHREADS 128
#define NWARPS (NTHREADS/32)
#define SPLIT 6             // CTAs per image
#define CHUNK ((NPA + SPLIT - 1) / SPLIT)   // 241 (<= 2*NTHREADS: two slots/thread)

__global__ void zero_out_kernel(float* out) { *out = 0.0f; }

__global__ __launch_bounds__(NTHREADS, 8)
void yolo_loss_kernel(const float* __restrict__ bbox_pred,
                      const float* __restrict__ iou_pred,
                      const float* __restrict__ score_pred,
                      const float* __restrict__ targets,
                      const float* __restrict__ anchors,
                      float* __restrict__ out)
{
    const int blk  = blockIdx.x;
    const int b    = blk / SPLIT;
    const int part = blk - b * SPLIT;
    const int tid  = threadIdx.x;

    __shared__ float4 gbox[GG];      // GT corners scaled by 17 (cell units)
    __shared__ float  garea[GG];     // scaled area (17w)*(17h)
    __shared__ float  thr06[GG];     // 0.6 * scaled area
    __shared__ float4 tarv[GG];      // off_x, off_y, w, h (original units)
    __shared__ int    gcls[GG];
    __shared__ short  selmap[NPA];
    __shared__ float  anc[AA][2];    // anchors / 17 (pred width in cell units = p.z*anc)
    __shared__ float  red[NWARPS];

    const int start = part * CHUNK;
    const int end   = (start + CHUNK < NPA) ? start + CHUNK : NPA;

    for (int i = start + tid; i < end; i += NTHREADS) selmap[i] = -1;
    if (tid < AA) {
        anc[tid][0] = anchors[tid*2+0] / 17.0f;
        anc[tid][1] = anchors[tid*2+1] / 17.0f;
    }
    __syncthreads();

    if (tid < GG) {
        const float* t = targets + ((size_t)b*GG + tid)*6;
        int   cls = (int)t[1];
        float x1 = t[2], y1 = t[3], x2 = t[4], y2 = t[5];
        gbox[tid] = make_float4(x1*17.0f, y1*17.0f, x2*17.0f, y2*17.0f);
        float w = x2 - x1, h = y2 - y1;
        float ar17 = (17.0f*w) * (17.0f*h);
        garea[tid] = ar17;
        thr06[tid] = 0.6f * ar17;
        float cxs = (x1 + x2) * 0.5f * 17.0f;
        float cys = (y1 + y2) * 0.5f * 17.0f;
        int ci = (int)floorf(cxs), cj = (int)floorf(cys);
        tarv[tid] = make_float4(cxs - (float)ci, cys - (float)cj, w, h);
        gcls[tid] = cls;
        // anchor argmax in original units (first-max tiebreak) — same as R4
        int best_a = 0; float best = -1.0f;
        float ar = w * h;
        #pragma unroll
        for (int a = 0; a < AA; a++) {
            float aw = anc[a][0], ah = anc[a][1];
            float inter = fminf(aw, w) * fminf(ah, h);
            float aiou  = inter / (aw*ah + ar - inter);
            if (aiou > best) { best = aiou; best_a = a; }
        }
        int cell = ci * SS + cj;
        selmap[cell*AA + best_a] = (short)tid;  // out-of-range writes never read
    }
    __syncthreads();

    const float* bb = bbox_pred  + (size_t)b * NPA * 4;
    const float* ip = iou_pred   + (size_t)b * NPA;
    const float* sp = score_pred + (size_t)b * NPA * CC;

    float acc = 0.0f;

    // two slots per thread, straight-line
    int  idx0 = start + tid;
    int  idx1 = start + NTHREADS + tid;
    bool v0 = idx0 < end;
    bool v1 = idx1 < end;
    int  s0 = v0 ? idx0 : start;
    int  s1 = v1 ? idx1 : start;

    float4 p0 = reinterpret_cast<const float4*>(bb)[s0];
    float4 p1 = reinterpret_cast<const float4*>(bb)[s1];

    int hw0 = s0 / AA, a0 = s0 - hw0*AA, i0 = hw0 / SS, j0 = hw0 - i0*SS;
    int hw1 = s1 / AA, a1 = s1 - hw1*AA, i1 = hw1 / SS, j1 = hw1 - i1*SS;

    // pred boxes in cell units: width = p.z * (anchors/17) = 17 * original width
    float aw0 = p0.z * anc[a0][0], ah0 = p0.w * anc[a0][1];
    float qx1_0 = p0.x + (float)i0 - 0.5f*aw0;
    float qx2_0 = p0.x + (float)i0 + 0.5f*aw0;
    float qy1_0 = p0.y + (float)j0 - 0.5f*ah0;
    float qy2_0 = p0.y + (float)j0 + 0.5f*ah0;
    float pa0 = aw0 * ah0;

    float aw1 = p1.z * anc[a1][0], ah1 = p1.w * anc[a1][1];
    float qx1_1 = p1.x + (float)i1 - 0.5f*aw1;
    float qx2_1 = p1.x + (float)i1 + 0.5f*aw1;
    float qy1_1 = p1.y + (float)j1 - 0.5f*ah1;
    float qy2_1 = p1.y + (float)j1 + 0.5f*ah1;
    float pa1 = aw1 * ah1;

    // m = max_k (1.6*inter_k - 0.6*garea_k); best_iou > 0.6 <=> m > 0.6*parea
    float m0 = -3.402823e38f, m1 = -3.402823e38f;
    #pragma unroll 4
    for (int k = 0; k < GG; k++) {
        float4 gb = gbox[k];
        float th  = thr06[k];
        {
            float lx = fmaxf(qx1_0, gb.x);
            float ly = fmaxf(qy1_0, gb.y);
            float rx = fminf(qx2_0, gb.z);
            float ry = fminf(qy2_0, gb.w);
            float iw = fmaxf(rx - lx, 0.0f);
            float ih = fmaxf(ry - ly, 0.0f);
            m0 = fmaxf(m0, fmaf(iw * ih, 1.6f, -th));
        }
        {
            float lx = fmaxf(qx1_1, gb.x);
            float ly = fmaxf(qy1_1, gb.y);
            float rx = fminf(qx2_1, gb.z);
            float ry = fminf(qy2_1, gb.w);
            float iw = fmaxf(rx - lx, 0.0f);
            float ih = fmaxf(ry - ly, 0.0f);
            m1 = fmaxf(m1, fmaf(iw * ih, 1.6f, -th));
        }
    }

    #pragma unroll
    for (int sl = 0; sl < 2; sl++) {
        bool  valid = sl ? v1 : v0;
        if (!valid) continue;
        int   sidx  = sl ? s1 : s0;
        float4 p    = sl ? p1 : p0;
        float m     = sl ? m1 : m0;
        float parea = sl ? pa1 : pa0;
        float qx1 = sl ? qx1_1 : qx1_0, qx2 = sl ? qx2_1 : qx2_0;
        float qy1 = sl ? qy1_1 : qy1_0, qy2 = sl ? qy2_1 : qy2_0;

        float ipv = ip[sidx];
        int   g   = (int)selmap[sidx];

        if (g < 0) {
            float d0 = 0.01f*(p.x - 0.5f);
            float d1 = 0.01f*(p.y - 0.5f);
            float d2 = 0.01f*(p.z - 1.0f);
            float d3 = 0.01f*(p.w - 1.0f);
            acc += d0*d0 + d1*d1 + d2*d2 + d3*d3;
            if (m <= 0.6f * parea) {      // best_iou <= 0.6 (scale-invariant)
                float q = ipv * ipv;
                acc += q * q;
            }
        } else {
            float4 gb = gbox[g];
            float lx = fmaxf(qx1, gb.x);
            float ly = fmaxf(qy1, gb.y);
            float rx = fminf(qx2, gb.z);
            float ry = fminf(qy2, gb.w);
            float iw = fmaxf(rx - lx, 0.0f);
            float ih = fmaxf(ry - ly, 0.0f);
            float inter = iw * ih;
            float iou_t = inter / (parea + garea[g] - inter);

            float4 tv = tarv[g];
            float d0 = p.x - tv.x;
            float d1 = p.y - tv.y;
            float d2 = p.z - tv.z;
            float d3 = p.w - tv.w;
            acc += d0*d0 + d1*d1 + d2*d2 + d3*d3;

            float mm = 5.0f * (1.0f - ipv);
            float d  = ipv - iou_t;
            acc += (mm*mm) * (d*d);

            int cls = gcls[g];
            const float* srow = sp + (size_t)sidx * CC;
            #pragma unroll
            for (int c = 0; c < CC; c++) {
                float t2 = (c == cls) ? 1.0f : 0.0f;
                float dd = srow[c] - t2;
                acc += dd * dd;
            }
        }
    }

    #pragma unroll
    for (int off = 16; off; off >>= 1)
        acc += __shfl_down_sync(0xffffffffu, acc, off);
    if ((tid & 31) == 0) red[tid >> 5] = acc;
    __syncthreads();
    if (tid < NWARPS) {
        float v = red[tid];
        #pragma unroll
        for (int off = (NWARPS/2); off; off >>= 1)
            v += __shfl_down_sync(0xffffffffu, v, off);
        if (tid == 0) atomicAdd(out, v * (1.0f / (float)GG));
    }
}

extern "C" void kernel_launch(void* const* d_in, const int* in_sizes, int n_in,
                              void* d_out, int out_size)
{
    const float* bbox    = (const float*)d_in[0];
    const float* iou     = (const float*)d_in[1];
    const float* score   = (const float*)d_in[2];
    const float* targets = (const float*)d_in[3];
    const float* anchors = (const float*)d_in[4];
    float* out = (float*)d_out;

    zero_out_kernel<<<1, 1>>>(out);
    yolo_loss_kernel<<<BIMG * SPLIT, NTHREADS>>>(bbox, iou, score, targets, anchors, out);
}